// round 2
// baseline (speedup 1.0000x reference)
#include <cuda_runtime.h>

// Problem constants
#define NB    32      // batch
#define NN    64      // objects
#define SSTR  260     // smem row stride (floats): even, 16B-aligned rows (260*4=1040? 1040%16=0 -> yes)

// Scratch (device globals: no allocation allowed)
__device__ float g_A[NB * NN * 256];   // x_i @ g1_w[0:65]
__device__ float g_C[NB * NN * 256];   // x_j @ g1_w[65:194] + g1_b
__device__ float g_xg[NB * 256];       // pooled sums

// ---------------- packed f32x2 helpers ----------------
__device__ __forceinline__ unsigned long long pack2(float lo, float hi) {
    unsigned long long r;
    asm("mov.b64 %0, {%1, %2};" : "=l"(r) : "f"(lo), "f"(hi));
    return r;
}
__device__ __forceinline__ void unpack2(unsigned long long v, float& lo, float& hi) {
    asm("mov.b64 {%0, %1}, %2;" : "=f"(lo), "=f"(hi) : "l"(v));
}
__device__ __forceinline__ unsigned long long fma2(unsigned long long a,
                                                   unsigned long long b,
                                                   unsigned long long c) {
    unsigned long long d;
    asm("fma.rn.f32x2 %0, %1, %2, %3;" : "=l"(d) : "l"(a), "l"(b), "l"(c));
    return d;
}

// ---------------- Phase 0: A/C precompute (g1 decomposition) ----------------
// A[b,i,o] = sum_{k<64} x_aux[b,i,k]*g1w[k,o] + i*g1w[64,o]
// C[b,j,o] = sum_{k<128} x_aux[b,j,k]*g1w[65+k,o] + j*g1w[193,o] + g1b[o]
__global__ void __launch_bounds__(256) precompute_AC(
    const float* __restrict__ x_aux,
    const float* __restrict__ g1w,
    const float* __restrict__ g1b)
{
    int bi = blockIdx.x;          // b*64 + i
    int i  = bi & 63;
    int o  = threadIdx.x;
    __shared__ float xs[128];
    const float* xr = x_aux + (size_t)bi * 128;
    if (o < 128) xs[o] = xr[o];
    __syncthreads();

    float fi = (float)i;
    float accA = fi * g1w[64 * 256 + o];
#pragma unroll 8
    for (int k = 0; k < 64; k++) accA = fmaf(xs[k], g1w[k * 256 + o], accA);
    g_A[bi * 256 + o] = accA;

    float accC = fmaf(fi, g1w[193 * 256 + o], g1b[o]);
#pragma unroll 8
    for (int k = 0; k < 128; k++) accC = fmaf(xs[k], g1w[(65 + k) * 256 + o], accC);
    g_C[bi * 256 + o] = accC;

    if (i == 0) g_xg[(bi >> 6) * 256 + o] = 0.f;   // zero the pooled accumulator
}

// ---------------- Fused 64x256 @ 256x256 layer (relu) ----------------
// Thread (tx 0..31, ty 0..7): rows ty*8+rr (rr<8), col pairs {2*tx+64*q, +1} (q<4).
__device__ __forceinline__ void mlp_layer(
    const float* __restrict__ in_s, float* __restrict__ out_s,
    float* __restrict__ Ws,
    const float* __restrict__ W, const float* __restrict__ bias,
    int tx, int ty, int tid)
{
    unsigned long long acc[8][4];
#pragma unroll
    for (int q = 0; q < 4; q++) {
        float2 bv = *(const float2*)(bias + 2 * tx + 64 * q);
        unsigned long long bb = pack2(bv.x, bv.y);
#pragma unroll
        for (int rr = 0; rr < 8; rr++) acc[rr][q] = bb;
    }

#pragma unroll 1
    for (int kt = 0; kt < 256; kt += 32) {
        __syncthreads();
        // stage W rows [kt, kt+32) : 8192 floats = 2048 float4, 8 per thread
        const float4* Wg = (const float4*)(W + kt * 256);
#pragma unroll
        for (int it = 0; it < 8; it++) {
            int v   = tid + 256 * it;     // float4 index within tile
            int row = v >> 6;             // 64 float4 per 256-float row
            int c4  = v & 63;
            *(float4*)(Ws + row * SSTR + c4 * 4) = Wg[v];
        }
        __syncthreads();

#pragma unroll 8
        for (int kk = 0; kk < 32; kk++) {
            int k = kt + kk;
            unsigned long long bv[4];
#pragma unroll
            for (int q = 0; q < 4; q++)
                bv[q] = *(const unsigned long long*)(Ws + kk * SSTR + 2 * tx + 64 * q);
#pragma unroll
            for (int rr = 0; rr < 8; rr++) {
                float a = in_s[(ty * 8 + rr) * SSTR + k];   // warp-broadcast
                unsigned long long a2 = pack2(a, a);
#pragma unroll
                for (int q = 0; q < 4; q++)
                    acc[rr][q] = fma2(a2, bv[q], acc[rr][q]);
            }
        }
    }

    // relu + write (no sync needed: out_s disjoint from in_s/Ws readers;
    // next layer's leading __syncthreads orders everything)
#pragma unroll
    for (int rr = 0; rr < 8; rr++) {
#pragma unroll
        for (int q = 0; q < 4; q++) {
            float lo, hi;
            unpack2(acc[rr][q], lo, hi);
            float2 v;
            v.x = fmaxf(lo, 0.f);
            v.y = fmaxf(hi, 0.f);
            *(float2*)(out_s + (ty * 8 + rr) * SSTR + 2 * tx + 64 * q) = v;
        }
    }
}

// ---------------- Phase 1: fused g2..g4 + pooling ----------------
// One CTA per (b, i): 64 pairs (all j), h1 = relu(A[b,i] + C[b,j]).
__global__ void __launch_bounds__(256) main_kernel(
    const float* __restrict__ g2w, const float* __restrict__ g2b,
    const float* __restrict__ g3w, const float* __restrict__ g3b,
    const float* __restrict__ g4w, const float* __restrict__ g4b)
{
    extern __shared__ float smem[];
    float* bufA = smem;                 // 64 x SSTR
    float* bufB = smem + 64 * SSTR;     // 64 x SSTR
    float* Ws   = smem + 128 * SSTR;    // 32 x SSTR

    int bi  = blockIdx.x;               // b*64 + i
    int b   = bi >> 6;
    int tid = threadIdx.x;
    int tx  = tid & 31;
    int ty  = tid >> 5;

    // h1 fill: bufA[j][o] = relu(A[b,i,o] + C[b,j,o])
    float a_o = g_A[bi * 256 + tid];
    const float* Cb = g_C + (size_t)b * NN * 256;
#pragma unroll 4
    for (int j = 0; j < 64; j++)
        bufA[j * SSTR + tid] = fmaxf(a_o + Cb[j * 256 + tid], 0.f);

    mlp_layer(bufA, bufB, Ws, g2w, g2b, tx, ty, tid);
    mlp_layer(bufB, bufA, Ws, g3w, g3b, tx, ty, tid);
    mlp_layer(bufA, bufB, Ws, g4w, g4b, tx, ty, tid);
    __syncthreads();

    // column-sum over the 64 pairs of this tile, accumulate into g_xg[b]
    float s = 0.f;
#pragma unroll 8
    for (int j = 0; j < 64; j++) s += bufB[j * SSTR + tid];
    atomicAdd(&g_xg[b * 256 + tid], s);
}

// ---------------- Phase 2: f-MLP (tiny: 32 rows) ----------------
__global__ void __launch_bounds__(256) f_mlp(
    const float* __restrict__ f1w, const float* __restrict__ f1b,
    const float* __restrict__ f2w, const float* __restrict__ f2b,
    const float* __restrict__ f3w, const float* __restrict__ f3b,
    float* __restrict__ out)
{
    int b = blockIdx.x;
    int o = threadIdx.x;
    __shared__ float xs[256];
    __shared__ float ys[256];

    xs[o] = g_xg[b * 256 + o];
    __syncthreads();

    float acc = f1b[o];
#pragma unroll 16
    for (int k = 0; k < 256; k++) acc = fmaf(xs[k], f1w[k * 256 + o], acc);
    ys[o] = fmaxf(acc, 0.f);
    __syncthreads();

    acc = f2b[o];
#pragma unroll 16
    for (int k = 0; k < 256; k++) acc = fmaf(ys[k], f2w[k * 256 + o], acc);
    xs[o] = fmaxf(acc, 0.f);
    __syncthreads();

    acc = f3b[o];
#pragma unroll 16
    for (int k = 0; k < 256; k++) acc = fmaf(xs[k], f3w[k * 256 + o], acc);
    out[b * 256 + o] = acc;
}

// ---------------- launch ----------------
extern "C" void kernel_launch(void* const* d_in, const int* in_sizes, int n_in,
                              void* d_out, int out_size)
{
    const float* x_aux = (const float*)d_in[0];
    const float* g1w   = (const float*)d_in[1];
    const float* g1b   = (const float*)d_in[2];
    const float* g2w   = (const float*)d_in[3];
    const float* g2b   = (const float*)d_in[4];
    const float* g3w   = (const float*)d_in[5];
    const float* g3b   = (const float*)d_in[6];
    const float* g4w   = (const float*)d_in[7];
    const float* g4b   = (const float*)d_in[8];
    const float* f1w   = (const float*)d_in[9];
    const float* f1b   = (const float*)d_in[10];
    const float* f2w   = (const float*)d_in[11];
    const float* f2b   = (const float*)d_in[12];
    const float* f3w   = (const float*)d_in[13];
    const float* f3b   = (const float*)d_in[14];
    float* out = (float*)d_out;

    const int smem_bytes = (128 * SSTR + 32 * SSTR) * 4;   // 166400 B
    cudaFuncSetAttribute(main_kernel, cudaFuncAttributeMaxDynamicSharedMemorySize, smem_bytes);

    precompute_AC<<<NB * NN, 256>>>(x_aux, g1w, g1b);
    main_kernel<<<NB * NN, 256, smem_bytes>>>(g2w, g2b, g3w, g3b, g4w, g4b);
    f_mlp<<<NB, 256>>>(f1w, f1b, f2w, f2b, f3w, f3b, out);
}